// round 6
// baseline (speedup 1.0000x reference)
#include <cuda_runtime.h>
#include <cuda_bf16.h>
#include <math.h>
#include <stdint.h>

// Problem dims
#define Bz 32
#define Sz 128
#define Ez 512
#define Hz 1024
#define Gz 4096   // 4*H
#define Lz 128
#define Vz 32000
#define TDz 126   // S-2
#define NBLK 128  // persistent grid size

// ---------------- scratch (device globals; no runtime allocation) ----------------
__device__ float g_Xe[Sz * Bz * Ez];
__device__ float g_Pe[(size_t)Sz * Bz * Gz];
__device__ float g_hse[(Sz + 1) * Bz * Hz];
__device__ float g_Xd[TDz * Bz * Ez];
__device__ float g_Pd[(size_t)TDz * Bz * Gz];
__device__ float g_hsd[(TDz + 1) * Bz * Hz];
__device__ unsigned g_bar;
// int8 2-level split buffers for the IMMA logits GEMM
__device__ int8_t g_Wq1[(size_t)Vz * Hz];
__device__ int8_t g_Wq2[(size_t)Vz * Hz];
__device__ int8_t g_Aq1[4096 * Hz];          // rows >= 4032 stay zero (device globals zero-init)
__device__ int8_t g_Aq2[4096 * Hz];
__device__ unsigned g_amaxA, g_amaxB;

// ---------------- f32x2 helpers ----------------
__device__ __forceinline__ unsigned long long pk2(float x, float y) {
    unsigned long long r;
    asm("mov.b64 %0, {%1,%2};" : "=l"(r) : "f"(x), "f"(y));
    return r;
}
__device__ __forceinline__ float2 upk2(unsigned long long v) {
    float2 r;
    asm("mov.b64 {%0,%1}, %2;" : "=f"(r.x), "=f"(r.y) : "l"(v));
    return r;
}
__device__ __forceinline__ unsigned long long ffma2(unsigned long long a, unsigned long long b,
                                                    unsigned long long c) {
    unsigned long long d;
    asm("fma.rn.f32x2 %0, %1, %2, %3;" : "=l"(d) : "l"(a), "l"(b), "l"(c));
    return d;
}
__device__ __forceinline__ float sigm(float x) { return 1.0f / (1.0f + expf(-x)); }

__device__ __forceinline__ uint32_t smem_u32(const void* p) {
    uint32_t a;
    asm("{ .reg .u64 t; cvta.to.shared.u64 t, %1; cvt.u32.u64 %0, t; }" : "=r"(a) : "l"(p));
    return a;
}

// ---------------- mma helpers (compute_103-safe PTX) ----------------
#define LDSM4(d, addr) \
    asm volatile("ldmatrix.sync.aligned.m8n8.x4.shared.b16 {%0,%1,%2,%3}, [%4];" \
        : "=r"((d)[0]), "=r"((d)[1]), "=r"((d)[2]), "=r"((d)[3]) : "r"(addr))

#define IMMA16832(c, a, b) \
    asm volatile("mma.sync.aligned.m16n8k32.row.col.s32.s8.s8.s32 " \
        "{%0,%1,%2,%3}, {%4,%5,%6,%7}, {%8,%9}, {%0,%1,%2,%3};" \
        : "+r"((c)[0]), "+r"((c)[1]), "+r"((c)[2]), "+r"((c)[3]) \
        : "r"((a)[0]), "r"((a)[1]), "r"((a)[2]), "r"((a)[3]), "r"((b)[0]), "r"((b)[1]))

// ---------------- grid barrier ----------------
__device__ __forceinline__ void grid_sync_(unsigned target) {
    __syncthreads();
    if (threadIdx.x == 0) {
        __threadfence();
        atomicAdd(&g_bar, 1u);
        unsigned v;
        do {
            asm volatile("ld.global.acquire.gpu.u32 %0, [%1];" : "=r"(v) : "l"(&g_bar));
        } while (v < target);
    }
    __syncthreads();
}

// ---------------- init: zero encoder h0, reset barrier + amaxes ----------------
__global__ void init_kernel(float* __restrict__ h0, int n) {
    int i = blockIdx.x * blockDim.x + threadIdx.x;
    int stride = gridDim.x * blockDim.x;
    for (; i < n; i += stride) h0[i] = 0.0f;
    if (blockIdx.x == 0 && threadIdx.x == 0) {
        g_bar = 0u;
        g_amaxA = 0u;
        g_amaxB = 0u;
    }
}

// ---------------- embedding gather ----------------
__global__ void embed_kernel(const int* __restrict__ tokens, const float* __restrict__ emb,
                             float* __restrict__ X, int T, int toff) {
    int total4 = T * Bz * (Ez / 4);
    int i = blockIdx.x * blockDim.x + threadIdx.x;
    int stride = gridDim.x * blockDim.x;
    const int E4 = Ez / 4;
    for (; i < total4; i += stride) {
        int e4 = i % E4;
        int r  = i / E4;
        int b  = r % Bz;
        int t  = r / Bz;
        int tok = tokens[b * Sz + t + toff];
        ((float4*)X)[i] = ((const float4*)(emb + (size_t)tok * Ez))[e4];
    }
}

// ---------------- amax reduction (positive float bits are order-preserving) ----------------
__global__ void amax_kernel(const float* __restrict__ x, int n4, unsigned* __restrict__ out) {
    int i = blockIdx.x * blockDim.x + threadIdx.x;
    int stride = gridDim.x * blockDim.x;
    float m = 0.f;
    for (; i < n4; i += stride) {
        float4 v = ((const float4*)x)[i];
        m = fmaxf(m, fmaxf(fmaxf(fabsf(v.x), fabsf(v.y)), fmaxf(fabsf(v.z), fabsf(v.w))));
    }
#pragma unroll
    for (int off = 16; off > 0; off >>= 1)
        m = fmaxf(m, __shfl_xor_sync(0xffffffffu, m, off));
    if ((threadIdx.x & 31) == 0) atomicMax(out, __float_as_uint(m));
}

// ---------------- int8 2-level quantization: x ~= s1*(q1 + q2/256) ----------------
__device__ __forceinline__ int q_clamp(float v) {
    int q = __float2int_rn(v);
    return max(-127, min(127, q));
}
__global__ void quant_kernel(const float* __restrict__ x, int8_t* __restrict__ q1,
                             int8_t* __restrict__ q2, int n4, const unsigned* __restrict__ amax) {
    float s1 = __uint_as_float(*amax) * (1.0f / 127.0f);
    float inv1 = 1.0f / s1;
    float inv2 = 256.0f / s1;
    int i = blockIdx.x * blockDim.x + threadIdx.x;
    int stride = gridDim.x * blockDim.x;
    for (; i < n4; i += stride) {
        float4 v = ((const float4*)x)[i];
        int a0 = q_clamp(v.x * inv1);
        int a1 = q_clamp(v.y * inv1);
        int a2 = q_clamp(v.z * inv1);
        int a3 = q_clamp(v.w * inv1);
        char4 c1;
        c1.x = (signed char)a0; c1.y = (signed char)a1;
        c1.z = (signed char)a2; c1.w = (signed char)a3;
        ((char4*)q1)[i] = c1;
        char4 c2;
        c2.x = (signed char)q_clamp((v.x - a0 * s1) * inv2);
        c2.y = (signed char)q_clamp((v.y - a1 * s1) * inv2);
        c2.z = (signed char)q_clamp((v.z - a2 * s1) * inv2);
        c2.w = (signed char)q_clamp((v.w - a3 * s1) * inv2);
        ((char4*)q2)[i] = c2;
    }
}

// ---------------- IMMA logits GEMM ----------------
// C[4032 x 32000] = A[4032 x 1024] @ W^T, int8 2-level split, int32 accum.
// Block tile 128(M) x 64(N) x 64(K bytes per stage, 2 x k32); warp tile 64x16.
// smem rows padded to 80B -> conflict-free ldmatrix (20r mod 32 all distinct).
#define ISTR   80
#define IA1    0
#define IA2    10240
#define IB1    20480
#define IB2    25600
#define ISTAGE 30720
#define IBIAS  (2 * ISTAGE)
#define SMEM_IMMA (2 * ISTAGE + 512)

__global__ __launch_bounds__(256, 1)
void imma_logits_kernel(const int8_t* __restrict__ Aq1, const int8_t* __restrict__ Aq2,
                        const int8_t* __restrict__ Wq1, const int8_t* __restrict__ Wq2,
                        const float* __restrict__ bias,
                        const unsigned* __restrict__ amaxA, const unsigned* __restrict__ amaxB,
                        float* __restrict__ out) {
    extern __shared__ char smem[];
    const uint32_t sbase = smem_u32(smem);
    const int tid = threadIdx.x;
    const int w = tid >> 5, lane = tid & 31;
    const int mtile = blockIdx.x;       // 0..31
    const int ntile = blockIdx.y;       // 0..499
    const int wm = (w & 1) * 64;
    const int wn = (w >> 1) * 16;

    if (tid < 64) ((float*)(smem + IBIAS))[tid] = bias[ntile * 64 + tid];

    // ---- G2S tasks: 1536 16B-chunks per k-stage, 6 per thread ----
    const int8_t* gsrc[6];
    uint32_t soff[6];
#pragma unroll
    for (int i = 0; i < 6; i++) {
        int t = tid + i * 256;
        if (t < 1024) {             // A: 128 rows x 2 levels x 4 chunks
            int lv = t >> 9, rr = t & 511;
            int r = rr >> 2, ch = rr & 3;
            gsrc[i] = (lv ? Aq2 : Aq1) + (size_t)(mtile * 128 + r) * Hz + ch * 16;
            soff[i] = (uint32_t)(lv * 10240 + r * ISTR + ch * 16);
        } else {                    // B: 64 rows x 2 levels x 4 chunks
            int t2 = t - 1024;
            int lv = t2 >> 8, rr = t2 & 255;
            int r = rr >> 2, ch = rr & 3;
            gsrc[i] = (lv ? Wq2 : Wq1) + (size_t)(ntile * 64 + r) * Hz + ch * 16;
            soff[i] = (uint32_t)(IB1 + lv * 5120 + r * ISTR + ch * 16);
        }
    }

    // ldmatrix lane bases (16B chunks)
    const uint32_t aLane = (uint32_t)(wm + (lane & 15)) * ISTR + (uint32_t)(lane >> 4) * 16;
    const uint32_t bLane = (uint32_t)(wn + ((lane >> 4) << 3) + (lane & 7)) * ISTR +
                           (uint32_t)((lane >> 3) & 1) * 16;

    int hi[4][2][4], lo[4][2][4];
#pragma unroll
    for (int i = 0; i < 4; i++)
#pragma unroll
        for (int j = 0; j < 2; j++)
#pragma unroll
            for (int q = 0; q < 4; q++) { hi[i][j][q] = 0; lo[i][j][q] = 0; }

    // prologue: stage 0
#pragma unroll
    for (int i = 0; i < 6; i++)
        *(uint4*)(smem + soff[i]) = *(const uint4*)gsrc[i];
    __syncthreads();

    for (int kt = 0; kt < 16; kt++) {
        const uint32_t stg = (uint32_t)(kt & 1) * ISTAGE;

        uint4 pf[6];
        if (kt < 15) {
#pragma unroll
            for (int i = 0; i < 6; i++)
                pf[i] = *(const uint4*)(gsrc[i] + (kt + 1) * 64);
        }

#pragma unroll
        for (int ks = 0; ks < 2; ks++) {
            const uint32_t kofs = (uint32_t)ks * 32;
            uint32_t fa1[4][4], fa2[4][4];
#pragma unroll
            for (int ma = 0; ma < 4; ma++) {
                uint32_t ad = sbase + stg + aLane + (uint32_t)ma * (16 * ISTR) + kofs;
                LDSM4(fa1[ma], ad + IA1);
                LDSM4(fa2[ma], ad + IA2);
            }
            uint32_t fb1[2][2], fb2[2][2];
            {
                uint32_t bd = sbase + stg + bLane + kofs;
                uint32_t t4[4];
                LDSM4(t4, bd + IB1);
                fb1[0][0] = t4[0]; fb1[0][1] = t4[1];
                fb1[1][0] = t4[2]; fb1[1][1] = t4[3];
                LDSM4(t4, bd + IB2);
                fb2[0][0] = t4[0]; fb2[0][1] = t4[1];
                fb2[1][0] = t4[2]; fb2[1][1] = t4[3];
            }
#pragma unroll
            for (int ma = 0; ma < 4; ma++)
#pragma unroll
                for (int at = 0; at < 2; at++) {
                    IMMA16832(hi[ma][at], fa1[ma], fb1[at]);
                    IMMA16832(lo[ma][at], fa1[ma], fb2[at]);
                    IMMA16832(lo[ma][at], fa2[ma], fb1[at]);
                }
        }

        if (kt < 15) {
            char* st = smem + ((kt + 1) & 1) * ISTAGE;
#pragma unroll
            for (int i = 0; i < 6; i++)
                *(uint4*)(st + soff[i]) = pf[i];
        }
        __syncthreads();
    }

    // ---- epilogue: scale, bias add, (t,b)->(b,t) remap ----
    const float s1a = __uint_as_float(*amaxA) * (1.0f / 127.0f);
    const float s1b = __uint_as_float(*amaxB) * (1.0f / 127.0f);
    const float s  = s1a * s1b;
    const float sl = s * (1.0f / 256.0f);
    const float* sb = (const float*)(smem + IBIAS);
#pragma unroll
    for (int ma = 0; ma < 4; ma++) {
        const int m0 = mtile * 128 + wm + ma * 16 + (lane >> 2);
#pragma unroll
        for (int at = 0; at < 2; at++) {
            const int cl = wn + at * 8 + (lane & 3) * 2;
            const float b0v = sb[cl], b1v = sb[cl + 1];
            const size_t col = (size_t)(ntile * 64 + cl);
            if (m0 < TDz * Bz) {
                int orow = (m0 & 31) * TDz + (m0 >> 5);
                float2 v;
                v.x = s * (float)hi[ma][at][0] + sl * (float)lo[ma][at][0] + b0v;
                v.y = s * (float)hi[ma][at][1] + sl * (float)lo[ma][at][1] + b1v;
                *(float2*)(out + (size_t)orow * Vz + col) = v;
            }
            const int m1 = m0 + 8;
            if (m1 < TDz * Bz) {
                int orow = (m1 & 31) * TDz + (m1 >> 5);
                float2 v;
                v.x = s * (float)hi[ma][at][2] + sl * (float)lo[ma][at][2] + b0v;
                v.y = s * (float)hi[ma][at][3] + sl * (float)lo[ma][at][3] + b1v;
                *(float2*)(out + (size_t)orow * Vz + col) = v;
            }
        }
    }
}

// ---------------- generic NT SGEMM (input projections) ----------------
__global__ __launch_bounds__(256, 2)
void sgemm_nt_kernel(const float* __restrict__ A, const float* __restrict__ W,
                     float* __restrict__ C, int M, int N, int K,
                     const float* __restrict__ bias1, const float* __restrict__ bias2) {
    __shared__ float As[16][132];
    __shared__ float Bs[16][132];

    const int n0 = blockIdx.x * 128;
    const int m0 = blockIdx.y * 128;
    const int tid = threadIdx.x;
    const int tx = tid & 15;
    const int ty = tid >> 4;
    const int lm = tid >> 2;
    const int lk4 = tid & 3;

    unsigned long long c2[8][4];
#pragma unroll
    for (int i = 0; i < 8; i++)
#pragma unroll
        for (int j = 0; j < 4; j++) c2[i][j] = 0ull;

    for (int k0 = 0; k0 < K; k0 += 16) {
#pragma unroll
        for (int r = 0; r < 2; r++) {
            int m = lm + r * 64;
            float4 v = make_float4(0.f, 0.f, 0.f, 0.f);
            int gm = m0 + m;
            if (gm < M) v = *(const float4*)(A + (size_t)gm * K + k0 + lk4 * 4);
            As[lk4 * 4 + 0][m] = v.x;
            As[lk4 * 4 + 1][m] = v.y;
            As[lk4 * 4 + 2][m] = v.z;
            As[lk4 * 4 + 3][m] = v.w;
        }
#pragma unroll
        for (int r = 0; r < 2; r++) {
            int n = lm + r * 64;
            float4 v = *(const float4*)(W + (size_t)(n0 + n) * K + k0 + lk4 * 4);
            Bs[lk4 * 4 + 0][n] = v.x;
            Bs[lk4 * 4 + 1][n] = v.y;
            Bs[lk4 * 4 + 2][n] = v.z;
            Bs[lk4 * 4 + 3][n] = v.w;
        }
        __syncthreads();

#pragma unroll
        for (int kk = 0; kk < 16; kk++) {
            float a[8];
            *(float4*)(&a[0]) = *(const float4*)(&As[kk][ty * 8]);
            *(float4*)(&a[4]) = *(const float4*)(&As[kk][ty * 8 + 4]);
            float b[8];
            *(float4*)(&b[0]) = *(const float4*)(&Bs[kk][tx * 8]);
            *(float4*)(&b[4]) = *(const float4*)(&Bs[kk][tx * 8 + 4]);
            unsigned long long b2[4];
#pragma unroll
            for (int j = 0; j < 4; j++) b2[j] = pk2(b[2 * j], b[2 * j + 1]);
#pragma unroll
            for (int i = 0; i < 8; i++) {
                unsigned long long a2 = pk2(a[i], a[i]);
#pragma unroll
                for (int j = 0; j < 4; j++) c2[i][j] = ffma2(a2, b2[j], c2[i][j]);
            }
        }
        __syncthreads();
    }

#pragma unroll
    for (int i = 0; i < 8; i++) {
        int m = m0 + ty * 8 + i;
        if (m >= M) continue;
        size_t rowbase = (size_t)m * N;
#pragma unroll
        for (int j = 0; j < 4; j++) {
            float2 v = upk2(c2[i][j]);
            int n = n0 + tx * 8 + 2 * j;
            C[rowbase + n]     = v.x + bias1[n] + bias2[n];
            C[rowbase + n + 1] = v.y + bias1[n + 1] + bias2[n + 1];
        }
    }
}

// ---------------- persistent LSTM building blocks ----------------
__device__ __forceinline__ void load_w(const float* __restrict__ Whh, int u, int lane,
                                       unsigned long long (&w2)[4][8][2]) {
#pragma unroll
    for (int r = 0; r < 4; r++) {
        const float4* wr = (const float4*)(Whh + (size_t)(r * Hz + u) * Hz);
#pragma unroll
        for (int j = 0; j < 8; j++) {
            float4 v = wr[j * 32 + lane];
            w2[r][j][0] = pk2(v.x, v.y);
            w2[r][j][1] = pk2(v.z, v.w);
        }
    }
}

__device__ __forceinline__ void dot4(const unsigned long long (&w2)[4][8][2],
                                     const ulonglong2* __restrict__ hb, int lane,
                                     unsigned long long (&acc)[4]) {
#pragma unroll
    for (int r = 0; r < 4; r++) acc[r] = 0ull;
#pragma unroll
    for (int j = 0; j < 8; j++) {
        ulonglong2 v = hb[j * 32 + lane];     // 4 floats, already packed as 2x f32x2
#pragma unroll
        for (int r = 0; r < 4; r++) {
            acc[r] = ffma2(w2[r][j][0], v.x, acc[r]);
            acc[r] = ffma2(w2[r][j][1], v.y, acc[r]);
        }
    }
}

__device__ __forceinline__ float reduce4(const unsigned long long (&acc)[4], int lane) {
    float2 p0 = upk2(acc[0]); float v0 = p0.x + p0.y;
    float2 p1 = upk2(acc[1]); float v1 = p1.x + p1.y;
    float2 p2 = upk2(acc[2]); float v2 = p2.x + p2.y;
    float2 p3 = upk2(acc[3]); float v3 = p3.x + p3.y;
    v0 += __shfl_xor_sync(0xffffffffu, v0, 1);
    v1 += __shfl_xor_sync(0xffffffffu, v1, 1);
    v2 += __shfl_xor_sync(0xffffffffu, v2, 1);
    v3 += __shfl_xor_sync(0xffffffffu, v3, 1);
    float a  = (lane & 1) ? v1 : v0;
    float bb = (lane & 1) ? v3 : v2;
    a  += __shfl_xor_sync(0xffffffffu, a, 2);
    bb += __shfl_xor_sync(0xffffffffu, bb, 2);
    float m = (lane & 2) ? bb : a;
    m += __shfl_xor_sync(0xffffffffu, m, 4);
    m += __shfl_xor_sync(0xffffffffu, m, 8);
    m += __shfl_xor_sync(0xffffffffu, m, 16);
    return m;
}

__device__ __forceinline__ float lstm_step_p(
    const unsigned long long (&w2)[4][8][2],
    const float* __restrict__ P, const float* __restrict__ hin,
    float* __restrict__ hout, float creg,
    float* __restrict__ sgf, float* __restrict__ sPf,
    int u0, int tid, int w, int lane)
{
#pragma unroll
    for (int k = 0; k < 4; k++) {
        int idx = tid + k * 256;
        int b = idx >> 5, c = idx & 31;
        sPf[b * 33 + c] = P[(size_t)b * Gz + (c >> 3) * Hz + u0 + (c & 7)];
    }

    const ulonglong2* h4 = (const ulonglong2*)hin;
    unsigned long long acc[2][4];
    dot4(w2, h4, lane, acc[0]);
#pragma unroll 2
    for (int b = 1; b < Bz; b++) {
        dot4(w2, h4 + b * 256, lane, acc[b & 1]);
        float m = reduce4(acc[(b - 1) & 1], lane);
        if (lane < 4) sgf[w * 132 + (b - 1) * 4 + lane] = m;
    }
    {
        float m = reduce4(acc[(Bz - 1) & 1], lane);
        if (lane < 4) sgf[w * 132 + (Bz - 1) * 4 + lane] = m;
    }
    __syncthreads();

    int ul = tid & 7, b = tid >> 3;
    float gi = sgf[ul * 132 + b * 4 + 0] + sPf[b * 33 +  0 + ul];
    float gf = sgf[ul * 132 + b * 4 + 1] + sPf[b * 33 +  8 + ul];
    float gg = sgf[ul * 132 + b * 4 + 2] + sPf[b * 33 + 16 + ul];
    float go = sgf[ul * 132 + b * 4 + 3] + sPf[b * 33 + 24 + ul];
    float cc = sigm(gf) * creg + sigm(gi) * tanhf(gg);
    float hh = sigm(go) * tanhf(cc);
    hout[b * Hz + u0 + ul] = hh;
    return cc;
}

__device__ void latent_dev(int b, int tid,
                           const int* __restrict__ tokens, const float* __restrict__ hs,
                           const float* __restrict__ Wmu, const float* __restrict__ bmu,
                           const float* __restrict__ Wlv, const float* __restrict__ blv,
                           const float* __restrict__ eps,
                           const float* __restrict__ Wl2h, const float* __restrict__ bl2h,
                           float* __restrict__ out_mean, float* __restrict__ out_lv,
                           float* __restrict__ hd0,
                           int* __restrict__ scnt, float* __restrict__ smean,
                           float* __restrict__ slv, float* __restrict__ szv) {
    int cnt = 0;
    if (tid < Sz) cnt = (tokens[b * Sz + tid] != 0) ? 1 : 0;
    scnt[tid] = cnt;
    __syncthreads();
    for (int off = 128; off >= 1; off >>= 1) {
        if (tid < off) scnt[tid] += scnt[tid + off];
        __syncthreads();
    }
    int last = scnt[0] - 1;
    if (last < 0) last = 0;

    const float* lh = hs + (size_t)(last + 1) * Bz * Hz + (size_t)b * Hz;
    {
        int j = tid & 127;
        const float* Wr = ((tid < 128) ? Wmu : Wlv) + (size_t)j * Hz;
        float acc = 0.f;
        const float4* l4 = (const float4*)lh;
        const float4* w4 = (const float4*)Wr;
#pragma unroll 4
        for (int k = 0; k < Hz / 4; k++) {
            float4 a = l4[k];
            float4 ww = w4[k];
            acc += a.x * ww.x + a.y * ww.y + a.z * ww.z + a.w * ww.w;
        }
        if (tid < 128) smean[j] = acc + bmu[j];
        else           slv[j]   = acc + blv[j];
    }
    __syncthreads();

    if (tid < 128) {
        float m = smean[tid];
        float lv = slv[tid];
        out_mean[b * Lz + tid] = m;
        out_lv[b * Lz + tid] = lv;
        szv[tid] = m + eps[b * Lz + tid] * expf(0.5f * lv);
    }
    __syncthreads();

#pragma unroll
    for (int r = 0; r < 4; r++) {
        int u = tid + r * 256;
        float acc = bl2h[u];
        const float* wr = Wl2h + (size_t)u * Lz;
#pragma unroll 4
        for (int l = 0; l < Lz; l++) acc += szv[l] * wr[l];
        hd0[b * Hz + u] = acc;
    }
}

__global__ __launch_bounds__(256, 1)
void lstm_persistent(const float* __restrict__ Whh_e, const float* __restrict__ Whh_d,
                     const float* __restrict__ Pe, const float* __restrict__ Pd,
                     float* __restrict__ hse, float* __restrict__ hsd,
                     const int* __restrict__ tokens,
                     const float* __restrict__ Wmu, const float* __restrict__ bmu,
                     const float* __restrict__ Wlv, const float* __restrict__ blv,
                     const float* __restrict__ eps,
                     const float* __restrict__ Wl2h, const float* __restrict__ bl2h,
                     float* __restrict__ out_mean, float* __restrict__ out_lv) {
    const int tid = threadIdx.x;
    const int w = tid >> 5;
    const int lane = tid & 31;
    const int u0 = blockIdx.x * 8;
    const int u = u0 + w;

    __shared__ float sgf[8 * 132];
    __shared__ float sPf[32 * 33];
    __shared__ int   scnt[256];
    __shared__ float smean[128], slvs[128], szv[128];

    unsigned long long w2[4][8][2];
    load_w(Whh_e, u, lane, w2);

    float creg = 0.f;
    unsigned epoch = 0;

    for (int t = 0; t < Sz; t++) {
        creg = lstm_step_p(w2, Pe + (size_t)t * Bz * Gz,
                           hse + (size_t)t * Bz * Hz,
                           hse + (size_t)(t + 1) * Bz * Hz,
                           creg, sgf, sPf, u0, tid, w, lane);
        epoch++;
        grid_sync_(epoch * NBLK);
    }

    load_w(Whh_d, u, lane, w2);
    if (blockIdx.x < 32) {
        latent_dev(blockIdx.x, tid, tokens, hse, Wmu, bmu, Wlv, blv, eps,
                   Wl2h, bl2h, out_mean, out_lv, hsd,
                   scnt, smean, slvs, szv);
    }
    epoch++;
    grid_sync_(epoch * NBLK);

    creg = 0.f;
    for (int t = 0; t < TDz; t++) {
        creg = lstm_step_p(w2, Pd + (size_t)t * Bz * Gz,
                           hsd + (size_t)t * Bz * Hz,
                           hsd + (size_t)(t + 1) * Bz * Hz,
                           creg, sgf, sPf, u0, tid, w, lane);
        if (t < TDz - 1) {
            epoch++;
            grid_sync_(epoch * NBLK);
        }
    }
}

// ---------------- launch ----------------
extern "C" void kernel_launch(void* const* d_in, const int* in_sizes, int n_in,
                              void* d_out, int out_size) {
    const int*   tokens  = (const int*)d_in[0];
    const float* emb_enc = (const float*)d_in[1];
    const float* Wih_e   = (const float*)d_in[2];
    const float* Whh_e   = (const float*)d_in[3];
    const float* bih_e   = (const float*)d_in[4];
    const float* bhh_e   = (const float*)d_in[5];
    const float* W_mu    = (const float*)d_in[6];
    const float* b_mu    = (const float*)d_in[7];
    const float* W_lv    = (const float*)d_in[8];
    const float* b_lv    = (const float*)d_in[9];
    const float* emb_dec = (const float*)d_in[10];
    const float* W_l2h   = (const float*)d_in[11];
    const float* b_l2h   = (const float*)d_in[12];
    const float* Wih_d   = (const float*)d_in[13];
    const float* Whh_d   = (const float*)d_in[14];
    const float* bih_d   = (const float*)d_in[15];
    const float* bhh_d   = (const float*)d_in[16];
    const float* W_out   = (const float*)d_in[17];
    const float* b_out   = (const float*)d_in[18];
    const float* epsv    = (const float*)d_in[19];

    float* out = (float*)d_out;
    const size_t LOGITS = (size_t)Bz * TDz * Vz;
    float* out_logits = out;
    float* out_mean   = out + LOGITS;
    float* out_lv     = out + LOGITS + (size_t)Bz * Lz;

    float *p_Xe, *p_Pe, *p_hse, *p_Xd, *p_Pd, *p_hsd;
    int8_t *p_Wq1, *p_Wq2, *p_Aq1, *p_Aq2;
    unsigned *p_amaxA, *p_amaxB;
    cudaGetSymbolAddress((void**)&p_Xe,  g_Xe);
    cudaGetSymbolAddress((void**)&p_Pe,  g_Pe);
    cudaGetSymbolAddress((void**)&p_hse, g_hse);
    cudaGetSymbolAddress((void**)&p_Xd,  g_Xd);
    cudaGetSymbolAddress((void**)&p_Pd,  g_Pd);
    cudaGetSymbolAddress((void**)&p_hsd, g_hsd);
    cudaGetSymbolAddress((void**)&p_Wq1, g_Wq1);
    cudaGetSymbolAddress((void**)&p_Wq2, g_Wq2);
    cudaGetSymbolAddress((void**)&p_Aq1, g_Aq1);
    cudaGetSymbolAddress((void**)&p_Aq2, g_Aq2);
    cudaGetSymbolAddress((void**)&p_amaxA, g_amaxA);
    cudaGetSymbolAddress((void**)&p_amaxB, g_amaxB);

    // 1) zero encoder h0 slot; reset grid barrier + amaxes
    init_kernel<<<64, 256>>>(p_hse, Bz * Hz);

    // 2) embeddings
    embed_kernel<<<2048, 256>>>(tokens, emb_enc, p_Xe, Sz, 0);
    embed_kernel<<<2048, 256>>>(tokens, emb_dec, p_Xd, TDz, 1);

    // 3) input projections (fp32 fma path)
    {
        dim3 grid(Gz / 128, (Sz * Bz + 127) / 128);
        sgemm_nt_kernel<<<grid, 256>>>(p_Xe, Wih_e, p_Pe, Sz * Bz, Gz, Ez, bih_e, bhh_e);
    }
    {
        dim3 grid(Gz / 128, (TDz * Bz + 127) / 128);
        sgemm_nt_kernel<<<grid, 256>>>(p_Xd, Wih_d, p_Pd, TDz * Bz, Gz, Ez, bih_d, bhh_d);
    }

    // 3b) W_out int8 2-level quantization (independent of everything else)
    amax_kernel<<<2048, 256>>>(W_out, (int)((size_t)Vz * Hz / 4), p_amaxB);
    quant_kernel<<<4096, 256>>>(W_out, p_Wq1, p_Wq2, (int)((size_t)Vz * Hz / 4), p_amaxB);

    // 4+5+6) recurrences + latent head, one persistent kernel
    lstm_persistent<<<NBLK, 256>>>(Whh_e, Whh_d, p_Pe, p_Pd, p_hse, p_hsd,
                                   tokens, W_mu, b_mu, W_lv, b_lv, epsv,
                                   W_l2h, b_l2h, out_mean, out_lv);

    // 6b) hd int8 quantization — A rows are CONTIGUOUS at hsd + 32*Hz
    amax_kernel<<<512, 256>>>(p_hsd + (size_t)Bz * Hz, TDz * Bz * Hz / 4, p_amaxA);
    quant_kernel<<<1024, 256>>>(p_hsd + (size_t)Bz * Hz, p_Aq1, p_Aq2,
                                TDz * Bz * Hz / 4, p_amaxA);

    // 7) logits via int8 IMMA 2-level split
    cudaFuncSetAttribute(imma_logits_kernel, cudaFuncAttributeMaxDynamicSharedMemorySize, SMEM_IMMA);
    {
        dim3 grid(32, 500);
        imma_logits_kernel<<<grid, 256, SMEM_IMMA>>>(p_Aq1, p_Aq2, p_Wq1, p_Wq2,
                                                     b_out, p_amaxA, p_amaxB, out_logits);
    }
}

// round 7
// speedup vs baseline: 1.0818x; 1.0818x over previous
#include <cuda_runtime.h>
#include <cuda_bf16.h>
#include <math.h>
#include <stdint.h>

// Problem dims
#define Bz 32
#define Sz 128
#define Ez 512
#define Hz 1024
#define Gz 4096   // 4*H
#define Lz 128
#define Vz 32000
#define TDz 126   // S-2
#define NBLK 128  // persistent grid size

// ---------------- scratch (device globals; no runtime allocation) ----------------
__device__ float g_Pe[(size_t)Sz * Bz * Gz];
__device__ float g_hse[(Sz + 1) * Bz * Hz];
__device__ float g_Pd[(size_t)4096 * Gz];          // padded to 4096 rows
__device__ float g_hsd[(TDz + 1) * Bz * Hz];
__device__ unsigned g_bar;
// bf16 split buffers
__device__ __nv_bfloat16 g_Whi[(size_t)Vz * Hz];
__device__ __nv_bfloat16 g_Wlo[(size_t)Vz * Hz];
__device__ __nv_bfloat16 g_Ahi[4096 * Hz];
__device__ __nv_bfloat16 g_Alo[4096 * Hz];
__device__ __nv_bfloat16 g_Xeh[4096 * Ez];
__device__ __nv_bfloat16 g_Xel[4096 * Ez];
__device__ __nv_bfloat16 g_Xdh[4096 * Ez];         // rows >= 4032 stay zero (BSS)
__device__ __nv_bfloat16 g_Xdl[4096 * Ez];
__device__ __nv_bfloat16 g_Wieh[Gz * Ez];
__device__ __nv_bfloat16 g_Wiel[Gz * Ez];
__device__ __nv_bfloat16 g_Widh[Gz * Ez];
__device__ __nv_bfloat16 g_Widl[Gz * Ez];

// ---------------- f32x2 helpers ----------------
__device__ __forceinline__ unsigned long long pk2(float x, float y) {
    unsigned long long r;
    asm("mov.b64 %0, {%1,%2};" : "=l"(r) : "f"(x), "f"(y));
    return r;
}
__device__ __forceinline__ float2 upk2(unsigned long long v) {
    float2 r;
    asm("mov.b64 {%0,%1}, %2;" : "=f"(r.x), "=f"(r.y) : "l"(v));
    return r;
}
__device__ __forceinline__ unsigned long long ffma2(unsigned long long a, unsigned long long b,
                                                    unsigned long long c) {
    unsigned long long d;
    asm("fma.rn.f32x2 %0, %1, %2, %3;" : "=l"(d) : "l"(a), "l"(b), "l"(c));
    return d;
}
__device__ __forceinline__ float sigm(float x) { return 1.0f / (1.0f + expf(-x)); }

__device__ __forceinline__ uint32_t smem_u32(const void* p) {
    uint32_t a;
    asm("{ .reg .u64 t; cvta.to.shared.u64 t, %1; cvt.u32.u64 %0, t; }" : "=r"(a) : "l"(p));
    return a;
}

// ---------------- mma.sync helpers (compute_103-safe, sm_80-era PTX) ----------------
#define LDSM4(d, addr) \
    asm volatile("ldmatrix.sync.aligned.m8n8.x4.shared.b16 {%0,%1,%2,%3}, [%4];" \
        : "=r"((d)[0]), "=r"((d)[1]), "=r"((d)[2]), "=r"((d)[3]) : "r"(addr))

#define MMA16816(c, a, b) \
    asm volatile("mma.sync.aligned.m16n8k16.row.col.f32.bf16.bf16.f32 " \
        "{%0,%1,%2,%3}, {%4,%5,%6,%7}, {%8,%9}, {%0,%1,%2,%3};" \
        : "+f"((c)[0]), "+f"((c)[1]), "+f"((c)[2]), "+f"((c)[3]) \
        : "r"((a)[0]), "r"((a)[1]), "r"((a)[2]), "r"((a)[3]), "r"((b)[0]), "r"((b)[1]))

// ---------------- grid barrier ----------------
__device__ __forceinline__ void grid_sync_(unsigned target) {
    __syncthreads();
    if (threadIdx.x == 0) {
        __threadfence();
        atomicAdd(&g_bar, 1u);
        unsigned v;
        do {
            asm volatile("ld.global.acquire.gpu.u32 %0, [%1];" : "=r"(v) : "l"(&g_bar));
        } while (v < target);
    }
    __syncthreads();
}

// ---------------- init ----------------
__global__ void init_kernel(float* __restrict__ h0, int n) {
    int i = blockIdx.x * blockDim.x + threadIdx.x;
    int stride = gridDim.x * blockDim.x;
    for (; i < n; i += stride) h0[i] = 0.0f;
    if (blockIdx.x == 0 && threadIdx.x == 0) g_bar = 0u;
}

// ---------------- embedding gather fused with bf16 hi/lo split ----------------
// X row (t*B+b), stride Ez; writes hi/lo bf16.
__global__ void embed_split_kernel(const int* __restrict__ tokens, const float* __restrict__ emb,
                                   __nv_bfloat16* __restrict__ hi, __nv_bfloat16* __restrict__ lo,
                                   int T, int toff) {
    int total4 = T * Bz * (Ez / 4);
    int i = blockIdx.x * blockDim.x + threadIdx.x;
    int stride = gridDim.x * blockDim.x;
    const int E4 = Ez / 4;
    for (; i < total4; i += stride) {
        int e4 = i % E4;
        int r  = i / E4;
        int b  = r % Bz;
        int t  = r / Bz;
        int tok = tokens[b * Sz + t + toff];
        float4 v = ((const float4*)(emb + (size_t)tok * Ez))[e4];
        __nv_bfloat16 h0 = __float2bfloat16(v.x);
        __nv_bfloat16 h1 = __float2bfloat16(v.y);
        __nv_bfloat16 h2 = __float2bfloat16(v.z);
        __nv_bfloat16 h3 = __float2bfloat16(v.w);
        __nv_bfloat162 ha; ha.x = h0; ha.y = h1;
        __nv_bfloat162 hb; hb.x = h2; hb.y = h3;
        ((__nv_bfloat162*)hi)[i * 2]     = ha;
        ((__nv_bfloat162*)hi)[i * 2 + 1] = hb;
        __nv_bfloat162 la, lb;
        la.x = __float2bfloat16(v.x - __bfloat162float(h0));
        la.y = __float2bfloat16(v.y - __bfloat162float(h1));
        lb.x = __float2bfloat16(v.z - __bfloat162float(h2));
        lb.y = __float2bfloat16(v.w - __bfloat162float(h3));
        ((__nv_bfloat162*)lo)[i * 2]     = la;
        ((__nv_bfloat162*)lo)[i * 2 + 1] = lb;
    }
}

// ---------------- generic bf16 hi/lo split ----------------
__global__ void convert_w_kernel(const float* __restrict__ W, __nv_bfloat16* __restrict__ hi,
                                 __nv_bfloat16* __restrict__ lo, int n4) {
    int i = blockIdx.x * blockDim.x + threadIdx.x;
    int stride = gridDim.x * blockDim.x;
    for (; i < n4; i += stride) {
        float4 v = ((const float4*)W)[i];
        __nv_bfloat16 h0 = __float2bfloat16(v.x);
        __nv_bfloat16 h1 = __float2bfloat16(v.y);
        __nv_bfloat16 h2 = __float2bfloat16(v.z);
        __nv_bfloat16 h3 = __float2bfloat16(v.w);
        __nv_bfloat162 ha; ha.x = h0; ha.y = h1;
        __nv_bfloat162 hb; hb.x = h2; hb.y = h3;
        ((__nv_bfloat162*)hi)[i * 2]     = ha;
        ((__nv_bfloat162*)hi)[i * 2 + 1] = hb;
        __nv_bfloat162 la, lb;
        la.x = __float2bfloat16(v.x - __bfloat162float(h0));
        la.y = __float2bfloat16(v.y - __bfloat162float(h1));
        lb.x = __float2bfloat16(v.z - __bfloat162float(h2));
        lb.y = __float2bfloat16(v.w - __bfloat162float(h3));
        ((__nv_bfloat162*)lo)[i * 2]     = la;
        ((__nv_bfloat162*)lo)[i * 2 + 1] = lb;
    }
}

// A row m (= t*Bz+b) = hsd[(m+32)*Hz + k]; rows >= 4032 zero-padded
__global__ void convert_a_kernel(const float* __restrict__ hsd, __nv_bfloat16* __restrict__ hi,
                                 __nv_bfloat16* __restrict__ lo) {
    int n4 = 4096 * Hz / 4;
    int i = blockIdx.x * blockDim.x + threadIdx.x;
    int stride = gridDim.x * blockDim.x;
    for (; i < n4; i += stride) {
        int e = i * 4;
        int m = e >> 10;
        int k = e & 1023;
        float4 v = make_float4(0.f, 0.f, 0.f, 0.f);
        if (m < TDz * Bz) v = *(const float4*)(hsd + (size_t)(m + 32) * Hz + k);
        __nv_bfloat16 h0 = __float2bfloat16(v.x);
        __nv_bfloat16 h1 = __float2bfloat16(v.y);
        __nv_bfloat16 h2 = __float2bfloat16(v.z);
        __nv_bfloat16 h3 = __float2bfloat16(v.w);
        __nv_bfloat162 ha; ha.x = h0; ha.y = h1;
        __nv_bfloat162 hb; hb.x = h2; hb.y = h3;
        ((__nv_bfloat162*)hi)[i * 2]     = ha;
        ((__nv_bfloat162*)hi)[i * 2 + 1] = hb;
        __nv_bfloat162 la, lb;
        la.x = __float2bfloat16(v.x - __bfloat162float(h0));
        la.y = __float2bfloat16(v.y - __bfloat162float(h1));
        lb.x = __float2bfloat16(v.z - __bfloat162float(h2));
        lb.y = __float2bfloat16(v.w - __bfloat162float(h3));
        ((__nv_bfloat162*)lo)[i * 2]     = la;
        ((__nv_bfloat162*)lo)[i * 2 + 1] = lb;
    }
}

// ---------------- bf16 3-split mma GEMM (templated) ----------------
// C[M x Nout] = A[M x KDIM] @ W^T + bias; block tile 128x128xKDIM, warp 64x32.
// MODE 0: logits — out[(b*TD+t)*Nout + n] = acc + bias1[n], guard m < TDz*Bz
// MODE 1: proj   — out[m*Nout + n] = acc + bias1[n] + bias2[n]
#define SSTR   80
#define SA_HI  0
#define SA_LO  10240
#define SB_HI  20480
#define SB_LO  30720
#define STAGE  40960
#define SBIAS  (2 * STAGE)
#define SMEM_MMA (2 * STAGE + 512)

template <int KDIM, int MODE>
__global__ __launch_bounds__(256, 2)
void mma3_kernel(const __nv_bfloat16* __restrict__ Ahi, const __nv_bfloat16* __restrict__ Alo,
                 const __nv_bfloat16* __restrict__ Whi, const __nv_bfloat16* __restrict__ Wlo,
                 const float* __restrict__ bias1, const float* __restrict__ bias2,
                 float* __restrict__ out, int Nout) {
    extern __shared__ char smem[];
    const uint32_t sbase = smem_u32(smem);
    const int tid = threadIdx.x;
    const int w = tid >> 5, lane = tid & 31;
    const int mtile = blockIdx.x;
    const int ntile = blockIdx.y;
    const int wm = (w & 1) * 64;
    const int wn = (w >> 1) * 32;

    if (tid < 128) {
        float bv = bias1[ntile * 128 + tid];
        if (MODE == 1) bv += bias2[ntile * 128 + tid];
        ((float*)(smem + SBIAS))[tid] = bv;
    }

    // ---- G2S: thread handles rows (tid>>2), (tid>>2)+64, 16B k-chunk (tid&3)*8 ----
    const int row = tid >> 2;
    const int ko  = (tid & 3) * 8;
    const __nv_bfloat16* gA0h = Ahi + (size_t)(mtile * 128 + row) * KDIM + ko;
    const __nv_bfloat16* gA1h = Ahi + (size_t)(mtile * 128 + row + 64) * KDIM + ko;
    const __nv_bfloat16* gA0l = Alo + (size_t)(mtile * 128 + row) * KDIM + ko;
    const __nv_bfloat16* gA1l = Alo + (size_t)(mtile * 128 + row + 64) * KDIM + ko;
    const __nv_bfloat16* gB0h = Whi + (size_t)(ntile * 128 + row) * KDIM + ko;
    const __nv_bfloat16* gB1h = Whi + (size_t)(ntile * 128 + row + 64) * KDIM + ko;
    const __nv_bfloat16* gB0l = Wlo + (size_t)(ntile * 128 + row) * KDIM + ko;
    const __nv_bfloat16* gB1l = Wlo + (size_t)(ntile * 128 + row + 64) * KDIM + ko;
    const uint32_t s0 = row * SSTR + ko * 2;
    const uint32_t s1 = (row + 64) * SSTR + ko * 2;

    const uint32_t aLane = (uint32_t)(wm + (lane & 15)) * SSTR + (uint32_t)(lane >> 4) * 16;
    const uint32_t bLane = (uint32_t)(wn + (lane & 7) + ((lane >> 4) << 3)) * SSTR +
                           (uint32_t)((lane >> 3) & 1) * 16;

    float acc[4][4][4];
#pragma unroll
    for (int i = 0; i < 4; i++)
#pragma unroll
        for (int j = 0; j < 4; j++)
#pragma unroll
            for (int q = 0; q < 4; q++) acc[i][j][q] = 0.f;

    {
        char* st = smem;
        *(uint4*)(st + SA_HI + s0) = *(const uint4*)gA0h;
        *(uint4*)(st + SA_HI + s1) = *(const uint4*)gA1h;
        *(uint4*)(st + SA_LO + s0) = *(const uint4*)gA0l;
        *(uint4*)(st + SA_LO + s1) = *(const uint4*)gA1l;
        *(uint4*)(st + SB_HI + s0) = *(const uint4*)gB0h;
        *(uint4*)(st + SB_HI + s1) = *(const uint4*)gB1h;
        *(uint4*)(st + SB_LO + s0) = *(const uint4*)gB0l;
        *(uint4*)(st + SB_LO + s1) = *(const uint4*)gB1l;
    }
    __syncthreads();

    const int NT = KDIM / 32;
    for (int kt = 0; kt < NT; kt++) {
        const uint32_t stg = (uint32_t)(kt & 1) * STAGE;

        uint4 r0, r1, r2, r3, r4, r5, r6, r7;
        if (kt < NT - 1) {
            const int go = (kt + 1) * 4;
            r0 = ((const uint4*)gA0h)[go]; r1 = ((const uint4*)gA1h)[go];
            r2 = ((const uint4*)gA0l)[go]; r3 = ((const uint4*)gA1l)[go];
            r4 = ((const uint4*)gB0h)[go]; r5 = ((const uint4*)gB1h)[go];
            r6 = ((const uint4*)gB0l)[go]; r7 = ((const uint4*)gB1l)[go];
        }

#pragma unroll
        for (int ks = 0; ks < 2; ks++) {
            const uint32_t kofs = (uint32_t)ks * 32;
            uint32_t aH[4][4], aL[4][4];
#pragma unroll
            for (int ma = 0; ma < 4; ma++) {
                uint32_t ad = sbase + stg + aLane + (uint32_t)ma * (16 * SSTR) + kofs;
                LDSM4(aH[ma], ad + SA_HI);
                LDSM4(aL[ma], ad + SA_LO);
            }
            uint32_t bH[4][2], bL[4][2];
#pragma unroll
            for (int nb2 = 0; nb2 < 2; nb2++) {
                uint32_t bd = sbase + stg + bLane + (uint32_t)nb2 * (16 * SSTR) + kofs;
                uint32_t t4[4];
                LDSM4(t4, bd + SB_HI);
                bH[nb2 * 2][0] = t4[0]; bH[nb2 * 2][1] = t4[1];
                bH[nb2 * 2 + 1][0] = t4[2]; bH[nb2 * 2 + 1][1] = t4[3];
                LDSM4(t4, bd + SB_LO);
                bL[nb2 * 2][0] = t4[0]; bL[nb2 * 2][1] = t4[1];
                bL[nb2 * 2 + 1][0] = t4[2]; bL[nb2 * 2 + 1][1] = t4[3];
            }
#pragma unroll
            for (int ma = 0; ma < 4; ma++)
#pragma unroll
                for (int nb = 0; nb < 4; nb++) {
                    MMA16816(acc[ma][nb], aH[ma], bH[nb]);
                    MMA16816(acc[ma][nb], aH[ma], bL[nb]);
                    MMA16816(acc[ma][nb], aL[ma], bH[nb]);
                }
        }

        if (kt < NT - 1) {
            char* st = smem + ((kt + 1) & 1) * STAGE;
            *(uint4*)(st + SA_HI + s0) = r0;
            *(uint4*)(st + SA_HI + s1) = r1;
            *(uint4*)(st + SA_LO + s0) = r2;
            *(uint4*)(st + SA_LO + s1) = r3;
            *(uint4*)(st + SB_HI + s0) = r4;
            *(uint4*)(st + SB_HI + s1) = r5;
            *(uint4*)(st + SB_LO + s0) = r6;
            *(uint4*)(st + SB_LO + s1) = r7;
        }
        __syncthreads();
    }

    // ---- epilogue ----
    const float* sb = (const float*)(smem + SBIAS);
#pragma unroll
    for (int ma = 0; ma < 4; ma++) {
        const int m0 = mtile * 128 + wm + ma * 16 + (lane >> 2);
#pragma unroll
        for (int nb = 0; nb < 4; nb++) {
            const int cl = wn + nb * 8 + (lane & 3) * 2;
            const float b0v = sb[cl], b1v = sb[cl + 1];
            const size_t col = (size_t)(ntile * 128 + cl);
            if (MODE == 0) {
                if (m0 < TDz * Bz) {
                    int orow = (m0 & 31) * TDz + (m0 >> 5);
                    float2 v;
                    v.x = acc[ma][nb][0] + b0v;
                    v.y = acc[ma][nb][1] + b1v;
                    *(float2*)(out + (size_t)orow * Nout + col) = v;
                }
                const int m1 = m0 + 8;
                if (m1 < TDz * Bz) {
                    int orow = (m1 & 31) * TDz + (m1 >> 5);
                    float2 v;
                    v.x = acc[ma][nb][2] + b0v;
                    v.y = acc[ma][nb][3] + b1v;
                    *(float2*)(out + (size_t)orow * Nout + col) = v;
                }
            } else {
                float2 v;
                v.x = acc[ma][nb][0] + b0v;
                v.y = acc[ma][nb][1] + b1v;
                *(float2*)(out + (size_t)m0 * Nout + col) = v;
                v.x = acc[ma][nb][2] + b0v;
                v.y = acc[ma][nb][3] + b1v;
                *(float2*)(out + (size_t)(m0 + 8) * Nout + col) = v;
            }
        }
    }
}

// ---------------- persistent LSTM building blocks ----------------
__device__ __forceinline__ void load_w(const float* __restrict__ Whh, int u, int lane,
                                       unsigned long long (&w2)[4][8][2]) {
#pragma unroll
    for (int r = 0; r < 4; r++) {
        const float4* wr = (const float4*)(Whh + (size_t)(r * Hz + u) * Hz);
#pragma unroll
        for (int j = 0; j < 8; j++) {
            float4 v = wr[j * 32 + lane];
            w2[r][j][0] = pk2(v.x, v.y);
            w2[r][j][1] = pk2(v.z, v.w);
        }
    }
}

__device__ __forceinline__ void dot4(const unsigned long long (&w2)[4][8][2],
                                     const ulonglong2* __restrict__ hb, int lane,
                                     unsigned long long (&acc)[4]) {
#pragma unroll
    for (int r = 0; r < 4; r++) acc[r] = 0ull;
#pragma unroll
    for (int j = 0; j < 8; j++) {
        ulonglong2 v = hb[j * 32 + lane];
#pragma unroll
        for (int r = 0; r < 4; r++) {
            acc[r] = ffma2(w2[r][j][0], v.x, acc[r]);
            acc[r] = ffma2(w2[r][j][1], v.y, acc[r]);
        }
    }
}

__device__ __forceinline__ float reduce4(const unsigned long long (&acc)[4], int lane) {
    float2 p0 = upk2(acc[0]); float v0 = p0.x + p0.y;
    float2 p1 = upk2(acc[1]); float v1 = p1.x + p1.y;
    float2 p2 = upk2(acc[2]); float v2 = p2.x + p2.y;
    float2 p3 = upk2(acc[3]); float v3 = p3.x + p3.y;
    v0 += __shfl_xor_sync(0xffffffffu, v0, 1);
    v1 += __shfl_xor_sync(0xffffffffu, v1, 1);
    v2 += __shfl_xor_sync(0xffffffffu, v2, 1);
    v3 += __shfl_xor_sync(0xffffffffu, v3, 1);
    float a  = (lane & 1) ? v1 : v0;
    float bb = (lane & 1) ? v3 : v2;
    a  += __shfl_xor_sync(0xffffffffu, a, 2);
    bb += __shfl_xor_sync(0xffffffffu, bb, 2);
    float m = (lane & 2) ? bb : a;
    m += __shfl_xor_sync(0xffffffffu, m, 4);
    m += __shfl_xor_sync(0xffffffffu, m, 8);
    m += __shfl_xor_sync(0xffffffffu, m, 16);
    return m;
}

__device__ __forceinline__ float lstm_step_p(
    const unsigned long long (&w2)[4][8][2],
    const float* __restrict__ P, const float* __restrict__ hin,
    float* __restrict__ hout, float creg,
    float* __restrict__ sgf, float* __restrict__ sPf,
    int u0, int tid, int w, int lane)
{
#pragma unroll
    for (int k = 0; k < 4; k++) {
        int idx = tid + k * 256;
        int b = idx >> 5, c = idx & 31;
        sPf[b * 33 + c] = P[(size_t)b * Gz + (c >> 3) * Hz + u0 + (c & 7)];
    }

    const ulonglong2* h4 = (const ulonglong2*)hin;
    unsigned long long acc[2][4];
    dot4(w2, h4, lane, acc[0]);
#pragma unroll 2
    for (int b = 1; b < Bz; b++) {
        dot4(w2, h4 + b * 256, lane, acc[b & 1]);
        float m = reduce4(acc[(b - 1) & 1], lane);
        if (lane < 4) sgf[w * 132 + (b - 1) * 4 + lane] = m;
    }
    {
        float m = reduce4(acc[(Bz - 1) & 1], lane);
        if (lane < 4) sgf[w * 132 + (Bz - 1) * 4 + lane] = m;
    }
    __syncthreads();

    int ul = tid & 7, b = tid >> 3;
    float gi = sgf[ul * 132 + b * 4 + 0] + sPf[b * 33 +  0 + ul];
    float gf = sgf[ul * 132 + b * 4 + 1] + sPf[b * 33 +  8 + ul];
    float gg = sgf[ul * 132 + b * 4 + 2] + sPf[b * 33 + 16 + ul];
    float go = sgf[ul * 132 + b * 4 + 3] + sPf[b * 33 + 24 + ul];
    float cc = sigm(gf) * creg + sigm(gi) * tanhf(gg);
    float hh = sigm(go) * tanhf(cc);
    hout[b * Hz + u0 + ul] = hh;
    return cc;
}

__device__ void latent_dev(int b, int tid,
                           const int* __restrict__ tokens, const float* __restrict__ hs,
                           const float* __restrict__ Wmu, const float* __restrict__ bmu,
                           const float* __restrict__ Wlv, const float* __restrict__ blv,
                           const float* __restrict__ eps,
                           const float* __restrict__ Wl2h, const float* __restrict__ bl2h,
                           float* __restrict__ out_mean, float* __restrict__ out_lv,
                           float* __restrict__ hd0,
                           int* __restrict__ scnt, float* __restrict__ smean,
                           float* __restrict__ slv, float* __restrict__ szv) {
    int cnt = 0;
    if (tid < Sz) cnt = (tokens[b * Sz + tid] != 0) ? 1 : 0;
    scnt[tid] = cnt;
    __syncthreads();
    for (int off = 128; off >= 1; off >>= 1) {
        if (tid < off) scnt[tid] += scnt[tid + off];
        __syncthreads();
    }
    int last = scnt[0] - 1;
    if (last < 0) last = 0;

    const float* lh = hs + (size_t)(last + 1) * Bz * Hz + (size_t)b * Hz;
    {
        int j = tid & 127;
        const float* Wr = ((tid < 128) ? Wmu : Wlv) + (size_t)j * Hz;
        float acc = 0.f;
        const float4* l4 = (const float4*)lh;
        const float4* w4 = (const float4*)Wr;
#pragma unroll 4
        for (int k = 0; k < Hz / 4; k++) {
            float4 a = l4[k];
            float4 ww = w4[k];
            acc += a.x * ww.x + a.y * ww.y + a.z * ww.z + a.w * ww.w;
        }
        if (tid < 128) smean[j] = acc + bmu[j];
        else           slv[j]   = acc + blv[j];
    }
    __syncthreads();

    if (tid < 128) {
        float m = smean[tid];
        float lv = slv[tid];
        out_mean[b * Lz + tid] = m;
        out_lv[b * Lz + tid] = lv;
        szv[tid] = m + eps[b * Lz + tid] * expf(0.5f * lv);
    }
    __syncthreads();

#pragma unroll
    for (int r = 0; r < 4; r++) {
        int u = tid + r * 256;
        float acc = bl2h[u];
        const float* wr = Wl2h + (size_t)u * Lz;
#pragma unroll 4
        for (int l = 0; l < Lz; l++) acc += szv[l] * wr[l];
        hd0[b * Hz + u] = acc;
    }
}

__global__ __launch_bounds__(256, 1)
void lstm_persistent(const float* __restrict__ Whh_e, const float* __restrict__ Whh_d,
                     const float* __restrict__ Pe, const float* __restrict__ Pd,
                     float* __restrict__ hse, float* __restrict__ hsd,
                     const int* __restrict__ tokens,
                     const float* __restrict__ Wmu, const float* __restrict__ bmu,
                     const float* __restrict__ Wlv, const float* __restrict__ blv,
                     const float* __restrict__ eps,
                     const float* __restrict__ Wl2h, const float* __restrict__ bl2h,
                     float* __restrict__ out_mean, float* __restrict__ out_lv) {
    const int tid = threadIdx.x;
    const int w = tid >> 5;
    const int lane = tid & 31;
    const int u0 = blockIdx.x * 8;
    const int u = u0 + w;

    __shared__ float sgf[8 * 132];
    __shared__ float sPf[32 * 33];
    __shared__ int   scnt[256];
    __shared__ float smean[128], slvs[128], szv[128];

    unsigned long long w2[4][8][2];
    load_w(Whh_e, u, lane, w2);

    float creg = 0.f;
    unsigned epoch = 0;

    for (int t = 0; t < Sz; t++) {
        creg = lstm_step_p(w2, Pe + (size_t)t * Bz * Gz,
                           hse + (size_t)t * Bz * Hz,
                           hse + (size_t)(t + 1) * Bz * Hz,
                           creg, sgf, sPf, u0, tid, w, lane);
        epoch++;
        grid_sync_(epoch * NBLK);
    }

    load_w(Whh_d, u, lane, w2);
    if (blockIdx.x < 32) {
        latent_dev(blockIdx.x, tid, tokens, hse, Wmu, bmu, Wlv, blv, eps,
                   Wl2h, bl2h, out_mean, out_lv, hsd,
                   scnt, smean, slvs, szv);
    }
    epoch++;
    grid_sync_(epoch * NBLK);

    creg = 0.f;
    for (int t = 0; t < TDz; t++) {
        creg = lstm_step_p(w2, Pd + (size_t)t * Bz * Gz,
                           hsd + (size_t)t * Bz * Hz,
                           hsd + (size_t)(t + 1) * Bz * Hz,
                           creg, sgf, sPf, u0, tid, w, lane);
        if (t < TDz - 1) {
            epoch++;
            grid_sync_(epoch * NBLK);
        }
    }
}

// ---------------- launch ----------------
extern "C" void kernel_launch(void* const* d_in, const int* in_sizes, int n_in,
                              void* d_out, int out_size) {
    const int*   tokens  = (const int*)d_in[0];
    const float* emb_enc = (const float*)d_in[1];
    const float* Wih_e   = (const float*)d_in[2];
    const float* Whh_e   = (const float*)d_in[3];
    const float* bih_e   = (const float*)d_in[4];
    const float* bhh_e   = (const float*)d_in[5];
    const float* W_mu    = (const float*)d_in[6];
    const float* b_mu    = (const float*)d_in[7];
    const float* W_lv    = (const float*)d_in[8];
    const float* b_lv    = (const float*)d_in[9];
    const float* emb_dec = (const float*)d_in[10];
    const float* W_l2h   = (const float*)d_in[11];
    const float* b_l2h   = (const float*)d_in[12];
    const float* Wih_d   = (const float*)d_in[13];
    const float* Whh_d   = (const float*)d_in[14];
    const float* bih_d   = (const float*)d_in[15];
    const float* bhh_d   = (const float*)d_in[16];
    const float* W_out   = (const float*)d_in[17];
    const float* b_out   = (const float*)d_in[18];
    const float* epsv    = (const float*)d_in[19];

    float* out = (float*)d_out;
    const size_t LOGITS = (size_t)Bz * TDz * Vz;
    float* out_logits = out;
    float* out_mean   = out + LOGITS;
    float* out_lv     = out + LOGITS + (size_t)Bz * Lz;

    float *p_Pe, *p_hse, *p_Pd, *p_hsd;
    __nv_bfloat16 *p_Whi, *p_Wlo, *p_Ahi, *p_Alo;
    __nv_bfloat16 *p_Xeh, *p_Xel, *p_Xdh, *p_Xdl;
    __nv_bfloat16 *p_Wieh, *p_Wiel, *p_Widh, *p_Widl;
    cudaGetSymbolAddress((void**)&p_Pe,  g_Pe);
    cudaGetSymbolAddress((void**)&p_hse, g_hse);
    cudaGetSymbolAddress((void**)&p_Pd,  g_Pd);
    cudaGetSymbolAddress((void**)&p_hsd, g_hsd);
    cudaGetSymbolAddress((void**)&p_Whi, g_Whi);
    cudaGetSymbolAddress((void**)&p_Wlo, g_Wlo);
    cudaGetSymbolAddress((void**)&p_Ahi, g_Ahi);
    cudaGetSymbolAddress((void**)&p_Alo, g_Alo);
    cudaGetSymbolAddress((void**)&p_Xeh, g_Xeh);
    cudaGetSymbolAddress((void**)&p_Xel, g_Xel);
    cudaGetSymbolAddress((void**)&p_Xdh, g_Xdh);
    cudaGetSymbolAddress((void**)&p_Xdl, g_Xdl);
    cudaGetSymbolAddress((void**)&p_Wieh, g_Wieh);
    cudaGetSymbolAddress((void**)&p_Wiel, g_Wiel);
    cudaGetSymbolAddress((void**)&p_Widh, g_Widh);
    cudaGetSymbolAddress((void**)&p_Widl, g_Widl);

    cudaFuncSetAttribute(mma3_kernel<512, 1>, cudaFuncAttributeMaxDynamicSharedMemorySize, SMEM_MMA);
    cudaFuncSetAttribute(mma3_kernel<1024, 0>, cudaFuncAttributeMaxDynamicSharedMemorySize, SMEM_MMA);

    // 1) zero encoder h0 slot; reset grid barrier
    init_kernel<<<64, 256>>>(p_hse, Bz * Hz);

    // 2) embeddings fused with bf16 split
    embed_split_kernel<<<1024, 256>>>(tokens, emb_enc, p_Xeh, p_Xel, Sz, 0);
    embed_split_kernel<<<1024, 256>>>(tokens, emb_dec, p_Xdh, p_Xdl, TDz, 1);

    // 2b) Wih bf16 splits
    convert_w_kernel<<<1024, 256>>>(Wih_e, p_Wieh, p_Wiel, Gz * Ez / 4);
    convert_w_kernel<<<1024, 256>>>(Wih_d, p_Widh, p_Widl, Gz * Ez / 4);

    // 3) input projections via bf16 3-split mma (K=512)
    {
        dim3 grid(32, 32);
        mma3_kernel<512, 1><<<grid, 256, SMEM_MMA>>>(p_Xeh, p_Xel, p_Wieh, p_Wiel,
                                                     bih_e, bhh_e, p_Pe, Gz);
        mma3_kernel<512, 1><<<grid, 256, SMEM_MMA>>>(p_Xdh, p_Xdl, p_Widh, p_Widl,
                                                     bih_d, bhh_d, p_Pd, Gz);
    }

    // 3b) W_out bf16 split
    convert_w_kernel<<<4096, 256>>>(W_out, p_Whi, p_Wlo, (int)((size_t)Vz * Hz / 4));

    // 4+5+6) recurrences + latent head, one persistent kernel
    lstm_persistent<<<NBLK, 256>>>(Whh_e, Whh_d, p_Pe, p_Pd, p_hse, p_hsd,
                                   tokens, W_mu, b_mu, W_lv, b_lv, epsv,
                                   W_l2h, b_l2h, out_mean, out_lv);

    // 6b) hd bf16 split
    convert_a_kernel<<<1024, 256>>>(p_hsd, p_Ahi, p_Alo);

    // 7) logits via bf16 3-split mma (K=1024)
    {
        dim3 grid(32, 250);
        mma3_kernel<1024, 0><<<grid, 256, SMEM_MMA>>>(p_Ahi, p_Alo, p_Whi, p_Wlo,
                                                      b_out, b_out, out_logits, Vz);
    }
}

// round 8
// speedup vs baseline: 1.7283x; 1.5977x over previous
#include <cuda_runtime.h>
#include <cuda_bf16.h>
#include <math.h>
#include <stdint.h>

// Problem dims
#define Bz 32
#define Sz 128
#define Ez 512
#define Hz 1024
#define Gz 4096   // 4*H
#define Lz 128
#define Vz 32000
#define TDz 126   // S-2
#define NBLK 128  // persistent grid size

// ---------------- scratch (device globals; no runtime allocation) ----------------
__device__ float g_Pe[(size_t)Sz * Bz * Gz];
__device__ float g_hse[(Sz + 1) * Bz * Hz];
__device__ float g_Pd[(size_t)4096 * Gz];          // padded to 4096 rows
__device__ float g_hsd[(TDz + 1) * Bz * Hz];
__device__ unsigned g_bar;
// bf16 split buffers
__device__ __nv_bfloat16 g_Whi[(size_t)Vz * Hz];
__device__ __nv_bfloat16 g_Wlo[(size_t)Vz * Hz];
__device__ __nv_bfloat16 g_Ahi[4096 * Hz];
__device__ __nv_bfloat16 g_Alo[4096 * Hz];
__device__ __nv_bfloat16 g_Xeh[4096 * Ez];
__device__ __nv_bfloat16 g_Xel[4096 * Ez];
__device__ __nv_bfloat16 g_Xdh[4096 * Ez];         // rows >= 4032 stay zero (BSS)
__device__ __nv_bfloat16 g_Xdl[4096 * Ez];
__device__ __nv_bfloat16 g_Wieh[Gz * Ez];
__device__ __nv_bfloat16 g_Wiel[Gz * Ez];
__device__ __nv_bfloat16 g_Widh[Gz * Ez];
__device__ __nv_bfloat16 g_Widl[Gz * Ez];

// ---------------- f32x2 helpers ----------------
__device__ __forceinline__ unsigned long long pk2(float x, float y) {
    unsigned long long r;
    asm("mov.b64 %0, {%1,%2};" : "=l"(r) : "f"(x), "f"(y));
    return r;
}
__device__ __forceinline__ float2 upk2(unsigned long long v) {
    float2 r;
    asm("mov.b64 {%0,%1}, %2;" : "=f"(r.x), "=f"(r.y) : "l"(v));
    return r;
}
__device__ __forceinline__ unsigned long long ffma2(unsigned long long a, unsigned long long b,
                                                    unsigned long long c) {
    unsigned long long d;
    asm("fma.rn.f32x2 %0, %1, %2, %3;" : "=l"(d) : "l"(a), "l"(b), "l"(c));
    return d;
}
__device__ __forceinline__ float sigm(float x) { return 1.0f / (1.0f + expf(-x)); }

__device__ __forceinline__ uint32_t smem_u32(const void* p) {
    uint32_t a;
    asm("{ .reg .u64 t; cvta.to.shared.u64 t, %1; cvt.u32.u64 %0, t; }" : "=r"(a) : "l"(p));
    return a;
}

// ---------------- mma.sync + cp.async helpers (compute_103-safe PTX) ----------------
#define LDSM4(d, addr) \
    asm volatile("ldmatrix.sync.aligned.m8n8.x4.shared.b16 {%0,%1,%2,%3}, [%4];" \
        : "=r"((d)[0]), "=r"((d)[1]), "=r"((d)[2]), "=r"((d)[3]) : "r"(addr))

#define MMA16816(c, a, b) \
    asm volatile("mma.sync.aligned.m16n8k16.row.col.f32.bf16.bf16.f32 " \
        "{%0,%1,%2,%3}, {%4,%5,%6,%7}, {%8,%9}, {%0,%1,%2,%3};" \
        : "+f"((c)[0]), "+f"((c)[1]), "+f"((c)[2]), "+f"((c)[3]) \
        : "r"((a)[0]), "r"((a)[1]), "r"((a)[2]), "r"((a)[3]), "r"((b)[0]), "r"((b)[1]))

#define CP_ASYNC16(smaddr, gptr) \
    asm volatile("cp.async.cg.shared.global [%0], [%1], 16;" :: "r"(smaddr), "l"(gptr))
#define CP_COMMIT() asm volatile("cp.async.commit_group;" ::: "memory")
#define CP_WAIT0()  asm volatile("cp.async.wait_group 0;" ::: "memory")

// ---------------- grid barrier ----------------
__device__ __forceinline__ void grid_sync_(unsigned target) {
    __syncthreads();
    if (threadIdx.x == 0) {
        __threadfence();
        atomicAdd(&g_bar, 1u);
        unsigned v;
        do {
            asm volatile("ld.global.acquire.gpu.u32 %0, [%1];" : "=r"(v) : "l"(&g_bar));
        } while (v < target);
    }
    __syncthreads();
}

// ---------------- init ----------------
__global__ void init_kernel(float* __restrict__ h0, int n) {
    int i = blockIdx.x * blockDim.x + threadIdx.x;
    int stride = gridDim.x * blockDim.x;
    for (; i < n; i += stride) h0[i] = 0.0f;
    if (blockIdx.x == 0 && threadIdx.x == 0) g_bar = 0u;
}

// ---------------- embedding gather fused with bf16 hi/lo split ----------------
__global__ void embed_split_kernel(const int* __restrict__ tokens, const float* __restrict__ emb,
                                   __nv_bfloat16* __restrict__ hi, __nv_bfloat16* __restrict__ lo,
                                   int T, int toff) {
    int total4 = T * Bz * (Ez / 4);
    int i = blockIdx.x * blockDim.x + threadIdx.x;
    int stride = gridDim.x * blockDim.x;
    const int E4 = Ez / 4;
    for (; i < total4; i += stride) {
        int e4 = i % E4;
        int r  = i / E4;
        int b  = r % Bz;
        int t  = r / Bz;
        int tok = tokens[b * Sz + t + toff];
        float4 v = ((const float4*)(emb + (size_t)tok * Ez))[e4];
        __nv_bfloat16 h0 = __float2bfloat16(v.x);
        __nv_bfloat16 h1 = __float2bfloat16(v.y);
        __nv_bfloat16 h2 = __float2bfloat16(v.z);
        __nv_bfloat16 h3 = __float2bfloat16(v.w);
        __nv_bfloat162 ha; ha.x = h0; ha.y = h1;
        __nv_bfloat162 hb; hb.x = h2; hb.y = h3;
        ((__nv_bfloat162*)hi)[i * 2]     = ha;
        ((__nv_bfloat162*)hi)[i * 2 + 1] = hb;
        __nv_bfloat162 la, lb;
        la.x = __float2bfloat16(v.x - __bfloat162float(h0));
        la.y = __float2bfloat16(v.y - __bfloat162float(h1));
        lb.x = __float2bfloat16(v.z - __bfloat162float(h2));
        lb.y = __float2bfloat16(v.w - __bfloat162float(h3));
        ((__nv_bfloat162*)lo)[i * 2]     = la;
        ((__nv_bfloat162*)lo)[i * 2 + 1] = lb;
    }
}

// ---------------- generic bf16 hi/lo split ----------------
__global__ void convert_w_kernel(const float* __restrict__ W, __nv_bfloat16* __restrict__ hi,
                                 __nv_bfloat16* __restrict__ lo, int n4) {
    int i = blockIdx.x * blockDim.x + threadIdx.x;
    int stride = gridDim.x * blockDim.x;
    for (; i < n4; i += stride) {
        float4 v = ((const float4*)W)[i];
        __nv_bfloat16 h0 = __float2bfloat16(v.x);
        __nv_bfloat16 h1 = __float2bfloat16(v.y);
        __nv_bfloat16 h2 = __float2bfloat16(v.z);
        __nv_bfloat16 h3 = __float2bfloat16(v.w);
        __nv_bfloat162 ha; ha.x = h0; ha.y = h1;
        __nv_bfloat162 hb; hb.x = h2; hb.y = h3;
        ((__nv_bfloat162*)hi)[i * 2]     = ha;
        ((__nv_bfloat162*)hi)[i * 2 + 1] = hb;
        __nv_bfloat162 la, lb;
        la.x = __float2bfloat16(v.x - __bfloat162float(h0));
        la.y = __float2bfloat16(v.y - __bfloat162float(h1));
        lb.x = __float2bfloat16(v.z - __bfloat162float(h2));
        lb.y = __float2bfloat16(v.w - __bfloat162float(h3));
        ((__nv_bfloat162*)lo)[i * 2]     = la;
        ((__nv_bfloat162*)lo)[i * 2 + 1] = lb;
    }
}

// A row m (= t*Bz+b) = hsd[(m+32)*Hz + k]; rows >= 4032 zero-padded
__global__ void convert_a_kernel(const float* __restrict__ hsd, __nv_bfloat16* __restrict__ hi,
                                 __nv_bfloat16* __restrict__ lo) {
    int n4 = 4096 * Hz / 4;
    int i = blockIdx.x * blockDim.x + threadIdx.x;
    int stride = gridDim.x * blockDim.x;
    for (; i < n4; i += stride) {
        int e = i * 4;
        int m = e >> 10;
        int k = e & 1023;
        float4 v = make_float4(0.f, 0.f, 0.f, 0.f);
        if (m < TDz * Bz) v = *(const float4*)(hsd + (size_t)(m + 32) * Hz + k);
        __nv_bfloat16 h0 = __float2bfloat16(v.x);
        __nv_bfloat16 h1 = __float2bfloat16(v.y);
        __nv_bfloat16 h2 = __float2bfloat16(v.z);
        __nv_bfloat16 h3 = __float2bfloat16(v.w);
        __nv_bfloat162 ha; ha.x = h0; ha.y = h1;
        __nv_bfloat162 hb; hb.x = h2; hb.y = h3;
        ((__nv_bfloat162*)hi)[i * 2]     = ha;
        ((__nv_bfloat162*)hi)[i * 2 + 1] = hb;
        __nv_bfloat162 la, lb;
        la.x = __float2bfloat16(v.x - __bfloat162float(h0));
        la.y = __float2bfloat16(v.y - __bfloat162float(h1));
        lb.x = __float2bfloat16(v.z - __bfloat162float(h2));
        lb.y = __float2bfloat16(v.w - __bfloat162float(h3));
        ((__nv_bfloat162*)lo)[i * 2]     = la;
        ((__nv_bfloat162*)lo)[i * 2 + 1] = lb;
    }
}

// ---------------- bf16 3-split mma GEMM (cp.async, occupancy 2) ----------------
// C[M x Nout] = A[M x KDIM] @ W^T + bias; block tile 128x128, warp 64x32.
// MODE 0: logits — out[(b*TD+t)*Nout + n], guard m < TDz*Bz
// MODE 1: proj   — out[m*Nout + n] = acc + bias1[n] + bias2[n]
#define SSTR   80
#define SA_HI  0
#define SA_LO  10240
#define SB_HI  20480
#define SB_LO  30720
#define STAGE  40960
#define SBIAS  (2 * STAGE)
#define SMEM_MMA (2 * STAGE + 512)

template <int KDIM, int MODE>
__global__ __launch_bounds__(256, 2)
void mma3_kernel(const __nv_bfloat16* __restrict__ Ahi, const __nv_bfloat16* __restrict__ Alo,
                 const __nv_bfloat16* __restrict__ Whi, const __nv_bfloat16* __restrict__ Wlo,
                 const float* __restrict__ bias1, const float* __restrict__ bias2,
                 float* __restrict__ out, int Nout) {
    extern __shared__ char smem[];
    const uint32_t sbase = smem_u32(smem);
    const int tid = threadIdx.x;
    const int w = tid >> 5, lane = tid & 31;
    const int mtile = blockIdx.x;
    const int ntile = blockIdx.y;
    const int wm = (w & 1) * 64;
    const int wn = (w >> 1) * 32;

    if (tid < 128) {
        float bv = bias1[ntile * 128 + tid];
        if (MODE == 1) bv += bias2[ntile * 128 + tid];
        ((float*)(smem + SBIAS))[tid] = bv;
    }

    // ---- G2S: thread owns rows (tid>>2), (tid>>2)+64, 16B k-chunk (tid&3)*8 ----
    const int row = tid >> 2;
    const int ko  = (tid & 3) * 8;
    const __nv_bfloat16* gA0h = Ahi + (size_t)(mtile * 128 + row) * KDIM + ko;
    const __nv_bfloat16* gA1h = Ahi + (size_t)(mtile * 128 + row + 64) * KDIM + ko;
    const __nv_bfloat16* gA0l = Alo + (size_t)(mtile * 128 + row) * KDIM + ko;
    const __nv_bfloat16* gA1l = Alo + (size_t)(mtile * 128 + row + 64) * KDIM + ko;
    const __nv_bfloat16* gB0h = Whi + (size_t)(ntile * 128 + row) * KDIM + ko;
    const __nv_bfloat16* gB1h = Whi + (size_t)(ntile * 128 + row + 64) * KDIM + ko;
    const __nv_bfloat16* gB0l = Wlo + (size_t)(ntile * 128 + row) * KDIM + ko;
    const __nv_bfloat16* gB1l = Wlo + (size_t)(ntile * 128 + row + 64) * KDIM + ko;
    const uint32_t s0 = sbase + row * SSTR + ko * 2;
    const uint32_t s1 = sbase + (row + 64) * SSTR + ko * 2;

    const uint32_t aLane = sbase + (uint32_t)(wm + (lane & 15)) * SSTR + (uint32_t)(lane >> 4) * 16;
    const uint32_t bLane = sbase + (uint32_t)(wn + (lane & 7) + ((lane >> 4) << 3)) * SSTR +
                           (uint32_t)((lane >> 3) & 1) * 16;

    float acc[4][4][4];
#pragma unroll
    for (int i = 0; i < 4; i++)
#pragma unroll
        for (int j = 0; j < 4; j++)
#pragma unroll
            for (int q = 0; q < 4; q++) acc[i][j][q] = 0.f;

    // prologue: stage 0 via cp.async
    CP_ASYNC16(s0 + SA_HI, gA0h); CP_ASYNC16(s1 + SA_HI, gA1h);
    CP_ASYNC16(s0 + SA_LO, gA0l); CP_ASYNC16(s1 + SA_LO, gA1l);
    CP_ASYNC16(s0 + SB_HI, gB0h); CP_ASYNC16(s1 + SB_HI, gB1h);
    CP_ASYNC16(s0 + SB_LO, gB0l); CP_ASYNC16(s1 + SB_LO, gB1l);
    CP_COMMIT();
    CP_WAIT0();
    __syncthreads();

    const int NT = KDIM / 32;
    for (int kt = 0; kt < NT; kt++) {
        const uint32_t stg = (uint32_t)(kt & 1) * STAGE;

        // issue async loads for kt+1 into the other stage
        if (kt < NT - 1) {
            const uint32_t nstg = (uint32_t)((kt + 1) & 1) * STAGE;
            const int go = (kt + 1) * 32;   // bf16 element advance
            CP_ASYNC16(s0 + nstg + SA_HI, gA0h + go); CP_ASYNC16(s1 + nstg + SA_HI, gA1h + go);
            CP_ASYNC16(s0 + nstg + SA_LO, gA0l + go); CP_ASYNC16(s1 + nstg + SA_LO, gA1l + go);
            CP_ASYNC16(s0 + nstg + SB_HI, gB0h + go); CP_ASYNC16(s1 + nstg + SB_HI, gB1h + go);
            CP_ASYNC16(s0 + nstg + SB_LO, gB0l + go); CP_ASYNC16(s1 + nstg + SB_LO, gB1l + go);
            CP_COMMIT();
        }

        // compute current stage
#pragma unroll
        for (int ks = 0; ks < 2; ks++) {
            const uint32_t kofs = (uint32_t)ks * 32;
            // B fragments first (stay live through the ma loop)
            uint32_t bH[4][2], bL[4][2];
#pragma unroll
            for (int nb2 = 0; nb2 < 2; nb2++) {
                uint32_t bd = stg + bLane + (uint32_t)nb2 * (16 * SSTR) + kofs;
                uint32_t t4[4];
                LDSM4(t4, bd + SB_HI);
                bH[nb2 * 2][0] = t4[0]; bH[nb2 * 2][1] = t4[1];
                bH[nb2 * 2 + 1][0] = t4[2]; bH[nb2 * 2 + 1][1] = t4[3];
                LDSM4(t4, bd + SB_LO);
                bL[nb2 * 2][0] = t4[0]; bL[nb2 * 2][1] = t4[1];
                bL[nb2 * 2 + 1][0] = t4[2]; bL[nb2 * 2 + 1][1] = t4[3];
            }
            // A fragments per-ma (short-lived -> low register pressure)
#pragma unroll
            for (int ma = 0; ma < 4; ma++) {
                uint32_t ad = stg + aLane + (uint32_t)ma * (16 * SSTR) + kofs;
                uint32_t aH[4], aL[4];
                LDSM4(aH, ad + SA_HI);
                LDSM4(aL, ad + SA_LO);
#pragma unroll
                for (int nb = 0; nb < 4; nb++) {
                    MMA16816(acc[ma][nb], aH, bH[nb]);
                    MMA16816(acc[ma][nb], aH, bL[nb]);
                    MMA16816(acc[ma][nb], aL, bH[nb]);
                }
            }
        }

        CP_WAIT0();
        __syncthreads();
    }

    // ---- epilogue ----
    const float* sb = (const float*)(smem + SBIAS);
#pragma unroll
    for (int ma = 0; ma < 4; ma++) {
        const int m0 = mtile * 128 + wm + ma * 16 + (lane >> 2);
#pragma unroll
        for (int nb = 0; nb < 4; nb++) {
            const int cl = wn + nb * 8 + (lane & 3) * 2;
            const float b0v = sb[cl], b1v = sb[cl + 1];
            const size_t col = (size_t)(ntile * 128 + cl);
            if (MODE == 0) {
                if (m0 < TDz * Bz) {
                    int orow = (m0 & 31) * TDz + (m0 >> 5);
                    float2 v;
                    v.x = acc[ma][nb][0] + b0v;
                    v.y = acc[ma][nb][1] + b1v;
                    *(float2*)(out + (size_t)orow * Nout + col) = v;
                }
                const int m1 = m0 + 8;
                if (m1 < TDz * Bz) {
                    int orow = (m1 & 31) * TDz + (m1 >> 5);
                    float2 v;
                    v.x = acc[ma][nb][2] + b0v;
                    v.y = acc[ma][nb][3] + b1v;
                    *(float2*)(out + (size_t)orow * Nout + col) = v;
                }
            } else {
                float2 v;
                v.x = acc[ma][nb][0] + b0v;
                v.y = acc[ma][nb][1] + b1v;
                *(float2*)(out + (size_t)m0 * Nout + col) = v;
                v.x = acc[ma][nb][2] + b0v;
                v.y = acc[ma][nb][3] + b1v;
                *(float2*)(out + (size_t)(m0 + 8) * Nout + col) = v;
            }
        }
    }
}

// ---------------- persistent LSTM building blocks ----------------
__device__ __forceinline__ void load_w(const float* __restrict__ Whh, int u, int lane,
                                       unsigned long long (&w2)[4][8][2]) {
#pragma unroll
    for (int r = 0; r < 4; r++) {
        const float4* wr = (const float4*)(Whh + (size_t)(r * Hz + u) * Hz);
#pragma unroll
        for (int j = 0; j < 8; j++) {
            float4 v = wr[j * 32 + lane];
            w2[r][j][0] = pk2(v.x, v.y);
            w2[r][j][1] = pk2(v.z, v.w);
        }
    }
}

__device__ __forceinline__ void dot4(const unsigned long long (&w2)[4][8][2],
                                     const ulonglong2* __restrict__ hb, int lane,
                                     unsigned long long (&acc)[4]) {
#pragma unroll
    for (int r = 0; r < 4; r++) acc[r] = 0ull;
#pragma unroll
    for (int j = 0; j < 8; j++) {
        ulonglong2 v = hb[j * 32 + lane];
#pragma unroll
        for (int r = 0; r < 4; r++) {
            acc[r] = ffma2(w2[r][j][0], v.x, acc[r]);
            acc[r] = ffma2(w2[r][j][1], v.y, acc[r]);
        }
    }
}

__device__ __forceinline__ float reduce4(const unsigned long long (&acc)[4], int lane) {
    float2 p0 = upk2(acc[0]); float v0 = p0.x + p0.y;
    float2 p1 = upk2(acc[1]); float v1 = p1.x + p1.y;
    float2 p2 = upk2(acc[2]); float v2 = p2.x + p2.y;
    float2 p3 = upk2(acc[3]); float v3 = p3.x + p3.y;
    v0 += __shfl_xor_sync(0xffffffffu, v0, 1);
    v1 += __shfl_xor_sync(0xffffffffu, v1, 1);
    v2 += __shfl_xor_sync(0xffffffffu, v2, 1);
    v3 += __shfl_xor_sync(0xffffffffu, v3, 1);
    float a  = (lane & 1) ? v1 : v0;
    float bb = (lane & 1) ? v3 : v2;
    a  += __shfl_xor_sync(0xffffffffu, a, 2);
    bb += __shfl_xor_sync(0xffffffffu, bb, 2);
    float m = (lane & 2) ? bb : a;
    m += __shfl_xor_sync(0xffffffffu, m, 4);
    m += __shfl_xor_sync(0xffffffffu, m, 8);
    m += __shfl_xor_sync(0xffffffffu, m, 16);
    return m;
}

__device__ __forceinline__ float lstm_step_p(
    const unsigned long long (&w2)[4][8][2],
    const float* __restrict__ P, const float* __restrict__ hin,
    float* __restrict__ hout, float creg,
    float* __restrict__ sgf, float* __restrict__ sPf,
    int u0, int tid, int w, int lane)
{
#pragma unroll
    for (int k = 0; k < 4; k++) {
        int idx = tid + k * 256;
        int b = idx >> 5, c = idx & 31;
        sPf[b * 33 + c] = P[(size_t)b * Gz + (c >> 3) * Hz + u0 + (c & 7)];
    }

    const ulonglong2* h4 = (const ulonglong2*)hin;
    unsigned long long acc[2][4];
    dot4(w2, h4, lane, acc[0]);
#pragma unroll 2
    for (int b = 1; b < Bz; b++) {
        dot4(w2, h4 + b * 256, lane, acc[b & 1]);
        float m = reduce4(acc[(b - 1) & 1], lane);
        if (lane < 4) sgf[w * 132 + (b - 1) * 4 + lane] = m;
    }
    {
        float m = reduce4(acc[(Bz - 1) & 1], lane);
        if (lane < 4) sgf[w * 132 + (Bz - 1) * 4 + lane] = m;
    }
    __syncthreads();

    int ul = tid & 7, b = tid >> 3;
    float gi = sgf[ul * 132 + b * 4 + 0] + sPf[b * 33 +  0 + ul];
    float gf = sgf[ul * 132 + b * 4 + 1] + sPf[b * 33 +  8 + ul];
    float gg = sgf[ul * 132 + b * 4 + 2] + sPf[b * 33 + 16 + ul];
    float go = sgf[ul * 132 + b * 4 + 3] + sPf[b * 33 + 24 + ul];
    float cc = sigm(gf) * creg + sigm(gi) * tanhf(gg);
    float hh = sigm(go) * tanhf(cc);
    hout[b * Hz + u0 + ul] = hh;
    return cc;
}

__device__ void latent_dev(int b, int tid,
                           const int* __restrict__ tokens, const float* __restrict__ hs,
                           const float* __restrict__ Wmu, const float* __restrict__ bmu,
                           const float* __restrict__ Wlv, const float* __restrict__ blv,
                           const float* __restrict__ eps,
                           const float* __restrict__ Wl2h, const float* __restrict__ bl2h,
                           float* __restrict__ out_mean, float* __restrict__ out_lv,
                           float* __restrict__ hd0,
                           int* __restrict__ scnt, float* __restrict__ smean,
                           float* __restrict__ slv, float* __restrict__ szv) {
    int cnt = 0;
    if (tid < Sz) cnt = (tokens[b * Sz + tid] != 0) ? 1 : 0;
    scnt[tid] = cnt;
    __syncthreads();
    for (int off = 128; off >= 1; off >>= 1) {
        if (tid < off) scnt[tid] += scnt[tid + off];
        __syncthreads();
    }
    int last = scnt[0] - 1;
    if (last < 0) last = 0;

    const float* lh = hs + (size_t)(last + 1) * Bz * Hz + (size_t)b * Hz;
    {
        int j = tid & 127;
        const float* Wr = ((tid < 128) ? Wmu : Wlv) + (size_t)j * Hz;
        float acc = 0.f;
        const float4* l4 = (const float4*)lh;
        const float4* w4 = (const float4*)Wr;
#pragma unroll 4
        for (int k = 0; k < Hz / 4; k++) {
            float4 a = l4[k];
            float4 ww = w4[k];
            acc += a.x * ww.x + a.y * ww.y + a.z * ww.z + a.w * ww.w;
        }
        if (tid < 128) smean[j] = acc + bmu[j];
        else           slv[j]   = acc + blv[j];
    }
    __syncthreads();

    if (tid < 128) {
        float m = smean[tid];
        float lv = slv[tid];
        out_mean[b * Lz + tid] = m;
        out_lv[b * Lz + tid] = lv;
        szv[tid] = m + eps[b * Lz + tid] * expf(0.5f * lv);
    }
    __syncthreads();

#pragma unroll
    for (int r = 0; r < 4; r++) {
        int u = tid + r * 256;
        float acc = bl2h[u];
        const float* wr = Wl2h + (size_t)u * Lz;
#pragma unroll 4
        for (int l = 0; l < Lz; l++) acc += szv[l] * wr[l];
        hd0[b * Hz + u] = acc;
    }
}

__global__ __launch_bounds__(256, 1)
void lstm_persistent(const float* __restrict__ Whh_e, const float* __restrict__ Whh_d,
                     const float* __restrict__ Pe, const float* __restrict__ Pd,
                     float* __restrict__ hse, float* __restrict__ hsd,
                     const int* __restrict__ tokens,
                     const float* __restrict__ Wmu, const float* __restrict__ bmu,
                     const float* __restrict__ Wlv, const float* __restrict__ blv,
                     const float* __restrict__ eps,
                     const float* __restrict__ Wl2h, const float* __restrict__ bl2h,
                     float* __restrict__ out_mean, float* __restrict__ out_lv) {
    const int tid = threadIdx.x;
    const int w = tid >> 5;
    const int lane = tid & 31;
    const int u0 = blockIdx.x * 8;
    const int u = u0 + w;

    __shared__ float sgf[8 * 132];
    __shared__ float sPf[32 * 33];
    __shared__ int   scnt[256];
    __shared__ float smean[128], slvs[128], szv[128];

    unsigned long long w2[4][8][2];
    load_w(Whh_e, u, lane, w2);

    float creg = 0.f;
    unsigned epoch = 0;

    for (int t = 0; t < Sz; t++) {
        creg = lstm_step_p(w2, Pe + (size_t)t * Bz * Gz,
                           hse + (size_t)t * Bz * Hz,
                           hse + (size_t)(t + 1) * Bz * Hz,
                           creg, sgf, sPf, u0, tid, w, lane);
        epoch++;
        grid_sync_(epoch * NBLK);
    }

    load_w(Whh_d, u, lane, w2);
    if (blockIdx.x < 32) {
        latent_dev(blockIdx.x, tid, tokens, hse, Wmu, bmu, Wlv, blv, eps,
                   Wl2h, bl2h, out_mean, out_lv, hsd,
                   scnt, smean, slvs, szv);
    }
    epoch++;
    grid_sync_(epoch * NBLK);

    creg = 0.f;
    for (int t = 0; t < TDz; t++) {
        creg = lstm_step_p(w2, Pd + (size_t)t * Bz * Gz,
                           hsd + (size_t)t * Bz * Hz,
                           hsd + (size_t)(t + 1) * Bz * Hz,
                           creg, sgf, sPf, u0, tid, w, lane);
        if (t < TDz - 1) {
            epoch++;
            grid_sync_(epoch * NBLK);
        }
    }
}

// ---------------- launch ----------------
extern "C" void kernel_launch(void* const* d_in, const int* in_sizes, int n_in,
                              void* d_out, int out_size) {
    const int*   tokens  = (const int*)d_in[0];
    const float* emb_enc = (const float*)d_in[1];
    const float* Wih_e   = (const float*)d_in[2];
    const float* Whh_e   = (const float*)d_in[3];
    const float* bih_e   = (const float*)d_in[4];
    const float* bhh_e   = (const float*)d_in[5];
    const float* W_mu    = (const float*)d_in[6];
    const float* b_mu    = (const float*)d_in[7];
    const float* W_lv    = (const float*)d_in[8];
    const float* b_lv    = (const float*)d_in[9];
    const float* emb_dec = (const float*)d_in[10];
    const float* W_l2h   = (const float*)d_in[11];
    const float* b_l2h   = (const float*)d_in[12];
    const float* Wih_d   = (const float*)d_in[13];
    const float* Whh_d   = (const float*)d_in[14];
    const float* bih_d   = (const float*)d_in[15];
    const float* bhh_d   = (const float*)d_in[16];
    const float* W_out   = (const float*)d_in[17];
    const float* b_out   = (const float*)d_in[18];
    const float* epsv    = (const float*)d_in[19];

    float* out = (float*)d_out;
    const size_t LOGITS = (size_t)Bz * TDz * Vz;
    float* out_logits = out;
    float* out_mean   = out + LOGITS;
    float* out_lv     = out + LOGITS + (size_t)Bz * Lz;

    float *p_Pe, *p_hse, *p_Pd, *p_hsd;
    __nv_bfloat16 *p_Whi, *p_Wlo, *p_Ahi, *p_Alo;
    __nv_bfloat16 *p_Xeh, *p_Xel, *p_Xdh, *p_Xdl;
    __nv_bfloat16 *p_Wieh, *p_Wiel, *p_Widh, *p_Widl;
    cudaGetSymbolAddress((void**)&p_Pe,  g_Pe);
    cudaGetSymbolAddress((void**)&p_hse, g_hse);
    cudaGetSymbolAddress((void**)&p_Pd,  g_Pd);
    cudaGetSymbolAddress((void**)&p_hsd, g_hsd);
    cudaGetSymbolAddress((void**)&p_Whi, g_Whi);
    cudaGetSymbolAddress((void**)&p_Wlo, g_Wlo);
    cudaGetSymbolAddress((void**)&p_Ahi, g_Ahi);
    cudaGetSymbolAddress((void**)&p_Alo, g_Alo);
    cudaGetSymbolAddress((void**)&p_Xeh, g_Xeh);
    cudaGetSymbolAddress((void**)&p_Xel, g_Xel);
    cudaGetSymbolAddress((void**)&p_Xdh, g_Xdh);
    cudaGetSymbolAddress((void**)&p_Xdl, g_Xdl);
    cudaGetSymbolAddress((void**)&p_Wieh, g_Wieh);
    cudaGetSymbolAddress((void**)&p_Wiel, g_Wiel);
    cudaGetSymbolAddress((void**)&p_Widh, g_Widh);
    cudaGetSymbolAddress((void**)&p_Widl, g_Widl);

    cudaFuncSetAttribute(mma3_kernel<512, 1>, cudaFuncAttributeMaxDynamicSharedMemorySize, SMEM_MMA);
    cudaFuncSetAttribute(mma3_kernel<1024, 0>, cudaFuncAttributeMaxDynamicSharedMemorySize, SMEM_MMA);

    // 1) zero encoder h0 slot; reset grid barrier
    init_kernel<<<64, 256>>>(p_hse, Bz * Hz);

    // 2) embeddings fused with bf16 split
    embed_split_kernel<<<1024, 256>>>(tokens, emb_enc, p_Xeh, p_Xel, Sz, 0);
    embed_split_kernel<<<1024, 256>>>(tokens, emb_dec, p_Xdh, p_Xdl, TDz, 1);

    // 2b) Wih bf16 splits
    convert_w_kernel<<<1024, 256>>>(Wih_e, p_Wieh, p_Wiel, Gz * Ez / 4);
    convert_w_kernel<<<1024, 256>>>(Wih_d, p_Widh, p_Widl, Gz * Ez / 4);

    // 3) input projections via bf16 3-split mma (K=512)
    {
        dim3 grid(32, 32);
        mma3_kernel<512, 1><<<grid, 256, SMEM_MMA>>>(p_Xeh, p_Xel, p_Wieh, p_Wiel,
                                                     bih_e, bhh_e, p_Pe, Gz);
        mma3_kernel<512, 1><<<grid, 256, SMEM_MMA>>>(p_Xdh, p_Xdl, p_Widh, p_Widl,
                                                     bih_d, bhh_d, p_Pd, Gz);
    }

    // 3b) W_out bf16 split
    convert_w_kernel<<<4096, 256>>>(W_out, p_Whi, p_Wlo, (int)((size_t)Vz * Hz / 4));

    // 4+5+6) recurrences + latent head, one persistent kernel
    lstm_persistent<<<NBLK, 256>>>(Whh_e, Whh_d, p_Pe, p_Pd, p_hse, p_hsd,
                                   tokens, W_mu, b_mu, W_lv, b_lv, epsv,
                                   W_l2h, b_l2h, out_mean, out_lv);

    // 6b) hd bf16 split
    convert_a_kernel<<<1024, 256>>>(p_hsd, p_Ahi, p_Alo);

    // 7) logits via bf16 3-split mma (K=1024)
    {
        dim3 grid(32, 250);
        mma3_kernel<1024, 0><<<grid, 256, SMEM_MMA>>>(p_Ahi, p_Alo, p_Whi, p_Wlo,
                                                      b_out, b_out, out_logits, Vz);
    }
}